// round 10
// baseline (speedup 1.0000x reference)
#include <cuda_runtime.h>
#include <math.h>

#define BATCH 64
#define NPTS  1024
#define KNNK  16
#define HID   64
#define TOTALPTS (BATCH * NPTS)

// Scratch (no allocations allowed)
__device__ float g_x1[TOTALPTS * HID];
__device__ float g_x2[TOTALPTS * HID];
__device__ float g_x3[TOTALPTS * HID];
__device__ float g_A [TOTALPTS * HID];   // x@(W1a-W1b)+b1
__device__ float g_Bm[TOTALPTS * HID];   // x@W1b
__device__ int   g_idx[TOTALPTS * KNNK];

__device__ __forceinline__ void gbar(int id, int cnt) {
    asm volatile("bar.sync %0, %1;" :: "r"(id), "r"(cnt) : "memory");
}

// ============================================================================
// kNN C=1 (cheap, keep simple per-thread scan)
// ============================================================================
__global__ __launch_bounds__(128, 4) void knn1_kernel(const float* __restrict__ x,
                                                      int* __restrict__ idx_out) {
    constexpr int PT = 128;
    __shared__ float xs[PT];

    int b   = blockIdx.x / (NPTS / PT);
    int t0  = (blockIdx.x % (NPTS / PT)) * PT;
    int tid = threadIdx.x;
    int i   = t0 + tid;
    const float* xb = x + (size_t)b * NPTS;

    float xi = xb[i];
    float sqi = xi * xi;

    float td[KNNK];
    int   ti[KNNK];
    #pragma unroll
    for (int k = 0; k < KNNK; k++) { td[k] = INFINITY; ti[k] = 0; }

    for (int jt = 0; jt < NPTS / PT; ++jt) {
        __syncthreads();
        xs[tid] = xb[jt * PT + tid];
        __syncthreads();
        for (int jj = 0; jj < PT; ++jj) {
            float xj = xs[jj];
            float d = (sqi + xj * xj) - 2.f * (xi * xj);
            if (d < td[KNNK - 1]) {
                td[KNNK - 1] = d;
                ti[KNNK - 1] = jt * PT + jj;
                #pragma unroll
                for (int s = KNNK - 1; s > 0; --s) {
                    if (td[s] < td[s - 1]) {
                        float tv = td[s]; td[s] = td[s - 1]; td[s - 1] = tv;
                        int   iv = ti[s]; ti[s] = ti[s - 1]; ti[s - 1] = iv;
                    }
                }
            }
        }
    }
    #pragma unroll
    for (int k = 0; k < KNNK; k++)
        idx_out[((size_t)b * NPTS + i) * KNNK + k] = ti[k];
}

// ============================================================================
// kNN C=64 v4: GEMM distance tiles, sized for 2 CTAs/SM (~100 KB smem).
// Block = 256 thr owns 64 queries; candidate tiles of 128 rows (8 tiles).
// GEMM: 16x16 thread grid, 4x8 register tiles (3 LDS.128 : 32 FMA).
// Selection: 128 threads, 2 per query (64 candidates each), top-16 in
// padded SMEM lists; final 2-way merge.
// ============================================================================
#define TKS  17    // padded top-k stride
#define DPAD 132   // distance tile row pitch (floats)
__host__ __device__ constexpr size_t knn64_smem() {
    return (size_t)(64 * 64        // xq_t  [k][m]
                  + 64 * 128       // xc_t  [k][n]
                  + 64 + 128       // sqq, sqc
                  + 256            // psc (norm partials)
                  + 64 * DPAD      // D
                  + 128 * TKS) * 4 // tdk
         + (size_t)(128 * TKS) * 4; // tik
}

__device__ __forceinline__ void topk_insert(float* td, int* ti, float d, int j) {
    int s = KNNK - 1;
    while (s > 0 && td[s - 1] > d) {
        td[s] = td[s - 1]; ti[s] = ti[s - 1]; --s;
    }
    td[s] = d; ti[s] = j;
}

__global__ __launch_bounds__(256, 2) void knn64_kernel(const float* __restrict__ x,
                                                       int* __restrict__ idx_out) {
    extern __shared__ __align__(16) float sm[];
    float* xq_t = sm;                  // [k][m] 64x64
    float* xc_t = xq_t + 64 * 64;      // [k][n] 64x128
    float* sqq  = xc_t + 64 * 128;     // 64
    float* sqc  = sqq + 64;            // 128
    float* psc  = sqc + 128;           // 256
    float* D    = psc + 256;           // 64 x DPAD
    float* tdk  = D + 64 * DPAD;       // 128 x TKS
    int*   tik  = (int*)(tdk + 128 * TKS);

    int tid = threadIdx.x;
    int b   = blockIdx.x >> 4;
    int q0  = (blockIdx.x & 15) * 64;
    const float* xb = x + (size_t)b * NPTS * 64;

    // ---- stage queries transposed (row = tid>>2, quarter = tid&3) ----
    {
        int row = tid >> 2, qtr = tid & 3;
        const float4* r = (const float4*)(xb + (size_t)(q0 + row) * 64 + qtr * 16);
        float s = 0.f;
        #pragma unroll
        for (int c4 = 0; c4 < 4; c4++) {
            float4 v = r[c4];
            int c = qtr * 16 + c4 * 4;
            xq_t[(c+0)*64 + row] = v.x; xq_t[(c+1)*64 + row] = v.y;
            xq_t[(c+2)*64 + row] = v.z; xq_t[(c+3)*64 + row] = v.w;
            s += v.x*v.x + v.y*v.y + v.z*v.z + v.w*v.w;
        }
        psc[tid] = s;
    }
    __syncthreads();
    if (tid < 64)
        sqq[tid] = (psc[tid*4] + psc[tid*4+1]) + (psc[tid*4+2] + psc[tid*4+3]);

    // top-k init
    if (tid < 128) {
        float* td0 = tdk + tid * TKS;
        #pragma unroll
        for (int k = 0; k < KNNK; k++) td0[k] = INFINITY;
    }
    float cmax = INFINITY;

    int tr = tid >> 4, tc = tid & 15;     // GEMM: 16 row-grps x 16 col-grps
    int m0 = tr * 4, n0 = tc * 8;
    int selq = tid >> 1, selh = tid & 1;  // selection: 2 thr/query

    for (int jt = 0; jt < 8; ++jt) {
        __syncthreads();
        {   // stage candidate tile transposed (row = tid>>1, half = tid&1)
            int row = tid >> 1, half = tid & 1;
            const float4* r = (const float4*)(xb + (size_t)(jt * 128 + row) * 64 + half * 32);
            float s = 0.f;
            #pragma unroll
            for (int c4 = 0; c4 < 8; c4++) {
                float4 v = r[c4];
                int c = half * 32 + c4 * 4;
                xc_t[(c+0)*128 + row] = v.x; xc_t[(c+1)*128 + row] = v.y;
                xc_t[(c+2)*128 + row] = v.z; xc_t[(c+3)*128 + row] = v.w;
                s += v.x*v.x + v.y*v.y + v.z*v.z + v.w*v.w;
            }
            psc[tid] = s;
        }
        __syncthreads();
        if (tid < 128) sqc[tid] = psc[2*tid] + psc[2*tid+1];
        __syncthreads();

        // GEMM: acc[r][c] = dot(xq[m0+r], xc[n0+c]), 4x8 tile
        float acc[4][8];
        #pragma unroll
        for (int r = 0; r < 4; r++)
            #pragma unroll
            for (int c = 0; c < 8; c++) acc[r][c] = 0.f;

        #pragma unroll 4
        for (int k = 0; k < 64; k++) {
            float4 a = *(const float4*)(xq_t + k * 64 + m0);
            float4 w01 = *(const float4*)(xc_t + k * 128 + n0);
            float4 w23 = *(const float4*)(xc_t + k * 128 + n0 + 4);
            float av[4] = {a.x, a.y, a.z, a.w};
            float wv[8] = {w01.x,w01.y,w01.z,w01.w,w23.x,w23.y,w23.z,w23.w};
            #pragma unroll
            for (int r = 0; r < 4; r++)
                #pragma unroll
                for (int c = 0; c < 8; c++) acc[r][c] += av[r] * wv[c];
        }

        // finalize distances + store tile
        {
            float4 s01 = *(const float4*)(sqc + n0);
            float4 s23 = *(const float4*)(sqc + n0 + 4);
            float sv[8] = {s01.x,s01.y,s01.z,s01.w,s23.x,s23.y,s23.z,s23.w};
            #pragma unroll
            for (int r = 0; r < 4; r++) {
                float sq = sqq[m0 + r];
                float4 o0, o1;
                o0.x = (sq + sv[0]) - 2.f * acc[r][0];
                o0.y = (sq + sv[1]) - 2.f * acc[r][1];
                o0.z = (sq + sv[2]) - 2.f * acc[r][2];
                o0.w = (sq + sv[3]) - 2.f * acc[r][3];
                o1.x = (sq + sv[4]) - 2.f * acc[r][4];
                o1.y = (sq + sv[5]) - 2.f * acc[r][5];
                o1.z = (sq + sv[6]) - 2.f * acc[r][6];
                o1.w = (sq + sv[7]) - 2.f * acc[r][7];
                *(float4*)(D + (size_t)(m0 + r) * DPAD + n0)     = o0;
                *(float4*)(D + (size_t)(m0 + r) * DPAD + n0 + 4) = o1;
            }
        }
        __syncthreads();

        // selection: 128 threads, each scans 64 candidates of its query
        if (tid < 128) {
            float* td0 = tdk + tid * TKS;
            int*   ti0 = tik + tid * TKS;
            const float* drow = D + (size_t)selq * DPAD + selh * 64;
            int jbase = jt * 128 + selh * 64;
            #pragma unroll 4
            for (int j4 = 0; j4 < 16; j4++) {
                float4 v = *(const float4*)(drow + j4 * 4);
                if (v.x < cmax) { topk_insert(td0, ti0, v.x, jbase + j4*4 + 0); cmax = td0[KNNK-1]; }
                if (v.y < cmax) { topk_insert(td0, ti0, v.y, jbase + j4*4 + 1); cmax = td0[KNNK-1]; }
                if (v.z < cmax) { topk_insert(td0, ti0, v.z, jbase + j4*4 + 2); cmax = td0[KNNK-1]; }
                if (v.w < cmax) { topk_insert(td0, ti0, v.w, jbase + j4*4 + 3); cmax = td0[KNNK-1]; }
            }
        }
    }
    __syncthreads();

    // merge the two per-query lists (downstream max-pool is order-invariant)
    if (tid < 64) {
        const float* dA = tdk + (2*tid)   * TKS;
        const int*   iA = tik + (2*tid)   * TKS;
        const float* dB = tdk + (2*tid+1) * TKS;
        const int*   iB = tik + (2*tid+1) * TKS;
        int ia = 0, ib = 0;
        int* outp = idx_out + ((size_t)b * NPTS + q0 + tid) * KNNK;
        #pragma unroll
        for (int k = 0; k < KNNK; k++) {
            float da = dA[ia], db = dB[ib];
            if (da <= db) { outp[k] = iA[ia]; ia++; }
            else          { outp[k] = iB[ib]; ib++; }
        }
    }
}

// ============================================================================
// Precompute: A = x@(W1a-W1b)+b1, Bm = x@W1b.  One GEMM [128 pts x C]@[C x 128]
// per block; 256 thr as 16x16 grid, 8x8 register tiles.
// ============================================================================
template <int C>
__host__ __device__ constexpr size_t pre_smem() {
    return (size_t)(2 * C * 128 + 64) * 4;
}

template <int C>
__global__ __launch_bounds__(256) void pre_kernel(
    const float* __restrict__ x, const float* __restrict__ w1,
    const float* __restrict__ b1,
    float* __restrict__ A, float* __restrict__ Bm) {
    extern __shared__ __align__(16) float sm[];
    float* xt  = sm;             // C x 128 (k-major)
    float* wc  = xt + C * 128;   // C x 128: [ W1a-W1b | W1b ]
    float* b1s = wc + C * 128;   // 64

    int tid = threadIdx.x;
    int p0  = blockIdx.x * 128;

    for (int u = tid; u < C * 128; u += 256) {
        int c = u >> 7, j = u & 127;
        float v;
        if (j < 64) v = w1[c * 64 + j] - w1[(C + c) * 64 + j];
        else        v = w1[(C + c) * 64 + (j - 64)];
        wc[u] = v;
    }
    if constexpr (C == 1) {
        if (tid < 128) xt[tid] = x[p0 + tid];
    } else {
        int row = tid >> 1, half = tid & 1;
        const float4* r = (const float4*)(x + (size_t)(p0 + row) * C + half * 32);
        #pragma unroll
        for (int c4 = 0; c4 < 8; c4++) {
            float4 v = r[c4];
            int c = half * 32 + c4 * 4;
            xt[(c+0)*128 + row] = v.x; xt[(c+1)*128 + row] = v.y;
            xt[(c+2)*128 + row] = v.z; xt[(c+3)*128 + row] = v.w;
        }
    }
    if (tid < 64) b1s[tid] = b1[tid];
    __syncthreads();

    int tr = tid >> 4, tc = tid & 15;
    int m0 = tr * 8, n0 = tc * 8;
    float acc[8][8];
    #pragma unroll
    for (int r = 0; r < 8; r++)
        #pragma unroll
        for (int c = 0; c < 8; c++) acc[r][c] = 0.f;

    #pragma unroll 4
    for (int k = 0; k < C; k++) {
        float4 a01 = *(const float4*)(xt + k * 128 + m0);
        float4 a23 = *(const float4*)(xt + k * 128 + m0 + 4);
        float4 w01 = *(const float4*)(wc + k * 128 + n0);
        float4 w23 = *(const float4*)(wc + k * 128 + n0 + 4);
        float av[8] = {a01.x,a01.y,a01.z,a01.w,a23.x,a23.y,a23.z,a23.w};
        float wv[8] = {w01.x,w01.y,w01.z,w01.w,w23.x,w23.y,w23.z,w23.w};
        #pragma unroll
        for (int r = 0; r < 8; r++)
            #pragma unroll
            for (int c = 0; c < 8; c++) acc[r][c] += av[r] * wv[c];
    }

    if (tc < 8) {
        #pragma unroll
        for (int r = 0; r < 8; r++) {
            int p = p0 + m0 + r;
            float4 o0, o1;
            o0.x = acc[r][0] + b1s[n0+0]; o0.y = acc[r][1] + b1s[n0+1];
            o0.z = acc[r][2] + b1s[n0+2]; o0.w = acc[r][3] + b1s[n0+3];
            o1.x = acc[r][4] + b1s[n0+4]; o1.y = acc[r][5] + b1s[n0+5];
            o1.z = acc[r][6] + b1s[n0+6]; o1.w = acc[r][7] + b1s[n0+7];
            *(float4*)(A + (size_t)p * 64 + n0)     = o0;
            *(float4*)(A + (size_t)p * 64 + n0 + 4) = o1;
        }
    } else {
        int nb = n0 - 64;
        #pragma unroll
        for (int r = 0; r < 8; r++) {
            int p = p0 + m0 + r;
            float4 o0 = {acc[r][0], acc[r][1], acc[r][2], acc[r][3]};
            float4 o1 = {acc[r][4], acc[r][5], acc[r][6], acc[r][7]};
            *(float4*)(Bm + (size_t)p * 64 + nb)     = o0;
            *(float4*)(Bm + (size_t)p * 64 + nb + 4) = o1;
        }
    }
}

// ============================================================================
// Edge stage 2: h1[edge] = relu(A[i] + Bm[nbr]); out[i] = max_k (h1@W2 + b2).
// 256 thr = 4 groups x 64; group does 4 points -> M=64 edge rows, N=64,
// 8x8 thread grid with 8x8 register tiles (16:1 FMA:LDS).
// nidx holds BATCH-LOCAL indices; convert with the block's batch base.
// ============================================================================
__host__ __device__ constexpr int eg_grp() { return 4096 + 256 + 512 + 64; }
__host__ __device__ constexpr size_t edge2_smem() {
    return (size_t)(4096 + 64 + 4 * eg_grp()) * 4;
}

__global__ __launch_bounds__(256, 2) void edge2_kernel(
    const float* __restrict__ A, const float* __restrict__ Bm,
    const int* __restrict__ nidx,
    const float* __restrict__ w2, const float* __restrict__ b2,
    float* __restrict__ out) {
    extern __shared__ __align__(16) float sm[];
    float* w2s = sm;           // 64x64 k-major (row-major w2 already is)
    float* b2s = w2s + 4096;   // 64
    float* grp = b2s + 64;

    int tid = threadIdx.x, g = tid >> 6, t = tid & 63;
    float* h1t = grp + g * eg_grp();   // [c][m] 64x64
    float* ais = h1t + 4096;           // 4x64
    float* red = ais + 256;            // 8x64
    int*   nbrs = (int*)(red + 512);   // 64

    for (int u = tid; u < 4096; u += 256) w2s[u] = w2[u];
    if (tid < 64) b2s[tid] = b2[tid];
    __syncthreads();

    int gp = blockIdx.x * 16 + g * 4;
    int batch_base = (gp >> 10) << 10;   // batch start (global point id)
    int bid = g + 1;

    #pragma unroll
    for (int pt = 0; pt < 4; pt++) ais[pt * 64 + t] = A[(size_t)(gp + pt) * 64 + t];
    nbrs[t] = nidx[(size_t)gp * KNNK + t];
    gbar(bid, 64);

    {   // gather + relu -> h1t (k-major)
        int pt = t >> 4;
        int nb = batch_base + nbrs[t];   // batch-local -> global
        const float4* bv4 = (const float4*)(Bm + (size_t)nb * 64);
        const float4* av4 = (const float4*)(ais + pt * 64);
        #pragma unroll
        for (int c4 = 0; c4 < 16; c4++) {
            float4 bv = bv4[c4], av = av4[c4];
            int c = c4 * 4;
            h1t[(c+0)*64 + t] = fmaxf(av.x + bv.x, 0.f);
            h1t[(c+1)*64 + t] = fmaxf(av.y + bv.y, 0.f);
            h1t[(c+2)*64 + t] = fmaxf(av.z + bv.z, 0.f);
            h1t[(c+3)*64 + t] = fmaxf(av.w + bv.w, 0.f);
        }
    }
    gbar(bid, 64);

    int tr = t >> 3, tc = t & 7;
    int m0 = tr * 8, n0 = tc * 8;
    float acc[8][8];
    #pragma unroll
    for (int r = 0; r < 8; r++)
        #pragma unroll
        for (int c = 0; c < 8; c++) acc[r][c] = 0.f;

    #pragma unroll 4
    for (int k = 0; k < HID; k++) {
        float4 a01 = *(const float4*)(h1t + k * 64 + m0);
        float4 a23 = *(const float4*)(h1t + k * 64 + m0 + 4);
        float4 w01 = *(const float4*)(w2s + k * 64 + n0);
        float4 w23 = *(const float4*)(w2s + k * 64 + n0 + 4);
        float av[8] = {a01.x,a01.y,a01.z,a01.w,a23.x,a23.y,a23.z,a23.w};
        float wv[8] = {w01.x,w01.y,w01.z,w01.w,w23.x,w23.y,w23.z,w23.w};
        #pragma unroll
        for (int r = 0; r < 8; r++)
            #pragma unroll
            for (int c = 0; c < 8; c++) acc[r][c] += av[r] * wv[c];
    }

    // partial max over this thread's 8 rows (8 neighbors of one point-half)
    float pm[8];
    #pragma unroll
    for (int c = 0; c < 8; c++) {
        float m = acc[0][c];
        #pragma unroll
        for (int r = 1; r < 8; r++) m = fmaxf(m, acc[r][c]);
        pm[c] = m;
    }
    *(float4*)(red + tr * 64 + n0)     = make_float4(pm[0], pm[1], pm[2], pm[3]);
    *(float4*)(red + tr * 64 + n0 + 4) = make_float4(pm[4], pm[5], pm[6], pm[7]);
    gbar(bid, 64);

    #pragma unroll
    for (int pt = 0; pt < 4; pt++) {
        float v = fmaxf(red[(2*pt) * 64 + t], red[(2*pt+1) * 64 + t]) + b2s[t];
        out[(size_t)(gp + pt) * 64 + t] = v;
    }
}

// ============================================================================
// Final MLP: 4-way split accumulators for ILP
// ============================================================================
#define MLP_GSZ (192 + 128 + 64 + 32 + 4)
__host__ __device__ constexpr size_t mlp_smem_bytes() {
    return (size_t)(192*128 + 128*64 + 64*32 + 32*2 + 128 + 64 + 32 + 4
                    + 2 * MLP_GSZ) * 4;
}

__global__ __launch_bounds__(256) void mlp_kernel(
    const float* __restrict__ x1, const float* __restrict__ x2,
    const float* __restrict__ x3,
    const float* __restrict__ mw1, const float* __restrict__ mb1,
    const float* __restrict__ mw2, const float* __restrict__ mb2,
    const float* __restrict__ mw3, const float* __restrict__ mb3,
    const float* __restrict__ mw4, const float* __restrict__ mb4,
    float* __restrict__ out) {
    extern __shared__ __align__(16) float sm[];
    float* w1s = sm;
    float* w2s = w1s + 192 * 128;
    float* w3s = w2s + 128 * 64;
    float* w4s = w3s + 64 * 32;
    float* b1s = w4s + 64;
    float* b2s = b1s + 128;
    float* b3s = b2s + 64;
    float* b4s = b3s + 32;
    float* grp = b4s + 4;

    int tid = threadIdx.x;
    int g   = tid >> 7;
    int t   = tid & 127;
    float* feat = grp + g * MLP_GSZ;
    float* h1   = feat + 192;
    float* h2   = h1 + 128;
    float* h3   = h2 + 64;
    float* oo   = h3 + 32;

    for (int u = tid; u < 192 * 128; u += 256) w1s[u] = mw1[u];
    for (int u = tid; u < 128 * 64;  u += 256) w2s[u] = mw2[u];
    for (int u = tid; u < 64 * 32;   u += 256) w3s[u] = mw3[u];
    if (tid < 64)  w4s[tid] = mw4[tid];
    if (tid < 128) b1s[tid] = mb1[tid];
    if (tid < 64)  b2s[tid] = mb2[tid];
    if (tid < 32)  b3s[tid] = mb3[tid];
    if (tid < 2)   b4s[tid] = mb4[tid];
    __syncthreads();

    constexpr int PTSG = 16;
    int base = blockIdx.x * (2 * PTSG) + g * PTSG;
    int bid  = g + 1;

    for (int p = 0; p < PTSG; ++p) {
        int gi = base + p;
        if (t < 64) {
            feat[t]       = x1[(size_t)gi * 64 + t];
            feat[64 + t]  = x2[(size_t)gi * 64 + t];
            feat[128 + t] = x3[(size_t)gi * 64 + t];
        }
        gbar(bid, 128);

        {
            float a0=0,a1=0,a2=0,a3=0;
            const float4* f4 = reinterpret_cast<const float4*>(feat);
            #pragma unroll 8
            for (int c4 = 0; c4 < 48; c4++) {
                float4 f = f4[c4];
                int c = c4 * 4;
                a0 += f.x * w1s[(c+0)*128 + t];
                a1 += f.y * w1s[(c+1)*128 + t];
                a2 += f.z * w1s[(c+2)*128 + t];
                a3 += f.w * w1s[(c+3)*128 + t];
            }
            h1[t] = fmaxf(((a0+a1)+(a2+a3)) + b1s[t], 0.f);
        }
        gbar(bid, 128);

        if (t < 64) {
            float a0=0,a1=0,a2=0,a3=0;
            const float4* f4 = reinterpret_cast<const float4*>(h1);
            #pragma unroll 8
            for (int c4 = 0; c4 < 32; c4++) {
                float4 f = f4[c4];
                int c = c4 * 4;
                a0 += f.x * w2s[(c+0)*64 + t];
                a1 += f.y * w2s[(c+1)*64 + t];
                a2 += f.z * w2s[(c+2)*64 + t];
                a3 += f.w * w2s[(c+3)*64 + t];
            }
            h2[t] = fmaxf(((a0+a1)+(a2+a3)) + b2s[t], 0.f);
        }
        gbar(bid, 128);

        if (t < 32) {
            float a0=0,a1=0,a2=0,a3=0;
            const float4* f4 = reinterpret_cast<const float4*>(h2);
            #pragma unroll
            for (int c4 = 0; c4 < 16; c4++) {
                float4 f = f4[c4];
                int c = c4 * 4;
                a0 += f.x * w3s[(c+0)*32 + t];
                a1 += f.y * w3s[(c+1)*32 + t];
                a2 += f.z * w3s[(c+2)*32 + t];
                a3 += f.w * w3s[(c+3)*32 + t];
            }
            h3[t] = fmaxf(((a0+a1)+(a2+a3)) + b3s[t], 0.f);
        }
        gbar(bid, 128);

        if (t < 2) {
            float acc = 0.f;
            #pragma unroll
            for (int c = 0; c < 32; c++) acc += h3[c] * w4s[c * 2 + t];
            oo[t] = acc + b4s[t];
        }
        gbar(bid, 128);

        if (t == 0) {
            float o0 = oo[0], o1 = oo[1];
            float m = fmaxf(o0, o1);
            float l = m + logf(expf(o0 - m) + expf(o1 - m));
            out[(size_t)gi * 2 + 0] = o0 - l;
            out[(size_t)gi * 2 + 1] = o1 - l;
        }
        gbar(bid, 128);
    }
}

// ============================================================================
// Launch
// ============================================================================
extern "C" void kernel_launch(void* const* d_in, const int* in_sizes, int n_in,
                              void* d_out, int out_size) {
    const float* x    = (const float*)d_in[0];
    const float* c1w1 = (const float*)d_in[1];
    const float* c1b1 = (const float*)d_in[2];
    const float* c1w2 = (const float*)d_in[3];
    const float* c1b2 = (const float*)d_in[4];
    const float* c2w1 = (const float*)d_in[5];
    const float* c2b1 = (const float*)d_in[6];
    const float* c2w2 = (const float*)d_in[7];
    const float* c2b2 = (const float*)d_in[8];
    const float* c3w1 = (const float*)d_in[9];
    const float* c3b1 = (const float*)d_in[10];
    const float* c3w2 = (const float*)d_in[11];
    const float* c3b2 = (const float*)d_in[12];
    const float* mw1  = (const float*)d_in[13];
    const float* mb1  = (const float*)d_in[14];
    const float* mw2  = (const float*)d_in[15];
    const float* mb2  = (const float*)d_in[16];
    const float* mw3  = (const float*)d_in[17];
    const float* mb3  = (const float*)d_in[18];
    const float* mw4  = (const float*)d_in[19];
    const float* mb4  = (const float*)d_in[20];
    float* out = (float*)d_out;

    float *x1p, *x2p, *x3p, *Ap, *Bp;
    int* idxp;
    cudaGetSymbolAddress((void**)&x1p, g_x1);
    cudaGetSymbolAddress((void**)&x2p, g_x2);
    cudaGetSymbolAddress((void**)&x3p, g_x3);
    cudaGetSymbolAddress((void**)&Ap,  g_A);
    cudaGetSymbolAddress((void**)&Bp,  g_Bm);
    cudaGetSymbolAddress((void**)&idxp, g_idx);

    size_t kn_smem  = knn64_smem();
    size_t p64_smem = pre_smem<64>();
    size_t p1_smem  = pre_smem<1>();
    size_t e2_smem  = edge2_smem();
    size_t ml_smem  = mlp_smem_bytes();
    cudaFuncSetAttribute(knn64_kernel,
                         cudaFuncAttributeMaxDynamicSharedMemorySize, (int)kn_smem);
    cudaFuncSetAttribute(pre_kernel<64>,
                         cudaFuncAttributeMaxDynamicSharedMemorySize, (int)p64_smem);
    cudaFuncSetAttribute(edge2_kernel,
                         cudaFuncAttributeMaxDynamicSharedMemorySize, (int)e2_smem);
    cudaFuncSetAttribute(mlp_kernel,
                         cudaFuncAttributeMaxDynamicSharedMemorySize, (int)ml_smem);

    dim3 knn1_grid(BATCH * (NPTS / 128));   // 512
    dim3 knn64_grid(BATCH * (NPTS / 64));   // 1024
    dim3 pre_grid(TOTALPTS / 128);          // 512
    dim3 e2_grid(TOTALPTS / 16);            // 4096
    dim3 mlp_grid(TOTALPTS / 32);           // 2048

    // conv1
    knn1_kernel<<<knn1_grid, 128>>>(x, idxp);
    pre_kernel<1><<<pre_grid, 256, p1_smem>>>(x, c1w1, c1b1, Ap, Bp);
    edge2_kernel<<<e2_grid, 256, e2_smem>>>(Ap, Bp, idxp, c1w2, c1b2, x1p);
    // conv2
    knn64_kernel<<<knn64_grid, 256, kn_smem>>>(x1p, idxp);
    pre_kernel<64><<<pre_grid, 256, p64_smem>>>(x1p, c2w1, c2b1, Ap, Bp);
    edge2_kernel<<<e2_grid, 256, e2_smem>>>(Ap, Bp, idxp, c2w2, c2b2, x2p);
    // conv3
    knn64_kernel<<<knn64_grid, 256, kn_smem>>>(x2p, idxp);
    pre_kernel<64><<<pre_grid, 256, p64_smem>>>(x2p, c3w1, c3b1, Ap, Bp);
    edge2_kernel<<<e2_grid, 256, e2_smem>>>(Ap, Bp, idxp, c3w2, c3b2, x3p);
    // head
    mlp_kernel<<<mlp_grid, 256, ml_smem>>>(x1p, x2p, x3p,
                                           mw1, mb1, mw2, mb2, mw3, mb3, mw4, mb4, out);
}

// round 12
// speedup vs baseline: 1.3740x; 1.3740x over previous
#include <cuda_runtime.h>
#include <math.h>

#define BATCH 64
#define NPTS  1024
#define KNNK  16
#define HID   64
#define TOTALPTS (BATCH * NPTS)

// Scratch (no allocations allowed)
__device__ float g_x1[TOTALPTS * HID];
__device__ float g_x2[TOTALPTS * HID];
__device__ float g_x3[TOTALPTS * HID];
__device__ float g_A [TOTALPTS * HID];   // x@(W1a-W1b)+b1
__device__ float g_Bm[TOTALPTS * HID];   // x@W1b
__device__ int   g_idx[TOTALPTS * KNNK];
__device__ float g_D [(size_t)BATCH * NPTS * NPTS];  // 256 MB distance scratch

__device__ __forceinline__ void gbar(int id, int cnt) {
    asm volatile("bar.sync %0, %1;" :: "r"(id), "r"(cnt) : "memory");
}

// ============================================================================
// kNN C=1 (cheap, per-thread scan)
// ============================================================================
__global__ __launch_bounds__(128, 4) void knn1_kernel(const float* __restrict__ x,
                                                      int* __restrict__ idx_out) {
    constexpr int PT = 128;
    __shared__ float xs[PT];

    int b   = blockIdx.x / (NPTS / PT);
    int t0  = (blockIdx.x % (NPTS / PT)) * PT;
    int tid = threadIdx.x;
    int i   = t0 + tid;
    const float* xb = x + (size_t)b * NPTS;

    float xi = xb[i];
    float sqi = xi * xi;

    float td[KNNK];
    int   ti[KNNK];
    #pragma unroll
    for (int k = 0; k < KNNK; k++) { td[k] = INFINITY; ti[k] = 0; }

    for (int jt = 0; jt < NPTS / PT; ++jt) {
        __syncthreads();
        xs[tid] = xb[jt * PT + tid];
        __syncthreads();
        for (int jj = 0; jj < PT; ++jj) {
            float xj = xs[jj];
            float d = (sqi + xj * xj) - 2.f * (xi * xj);
            if (d < td[KNNK - 1]) {
                td[KNNK - 1] = d;
                ti[KNNK - 1] = jt * PT + jj;
                #pragma unroll
                for (int s = KNNK - 1; s > 0; --s) {
                    if (td[s] < td[s - 1]) {
                        float tv = td[s]; td[s] = td[s - 1]; td[s - 1] = tv;
                        int   iv = ti[s]; ti[s] = ti[s - 1]; ti[s - 1] = iv;
                    }
                }
            }
        }
    }
    #pragma unroll
    for (int k = 0; k < KNNK; k++)
        idx_out[((size_t)b * NPTS + i) * KNNK + k] = ti[k];
}

// ============================================================================
// Distance GEMM: D[b][i][j] = |x_i|^2 + |x_j|^2 - 2 x_i.x_j  for C=64.
// One 128x128 output tile per block (grid 64 batches x 8 x 8 tiles).
// Pure GEMM: 16x16 thread grid, 8x8 register tiles, single barrier phase.
// ============================================================================
__host__ __device__ constexpr size_t dist_smem() {
    return (size_t)(64 * 128 + 64 * 128 + 128 + 128 + 512) * 4;  // ~68.5 KB
}

__global__ __launch_bounds__(256, 2) void dist_kernel(const float* __restrict__ x,
                                                      float* __restrict__ Dout) {
    extern __shared__ __align__(16) float sm[];
    float* xq_t = sm;                  // [k][m] 64x128
    float* xc_t = xq_t + 64 * 128;     // [k][n] 64x128
    float* sqq  = xc_t + 64 * 128;     // 128
    float* sqc  = sqq + 128;           // 128
    float* psc  = sqc + 128;           // 512 (q partials, c partials)

    int tid = threadIdx.x;
    int b   = blockIdx.x >> 6;
    int bq  = (blockIdx.x >> 3) & 7;
    int bc  = blockIdx.x & 7;
    int q0  = bq * 128, c0 = bc * 128;
    const float* xb = x + (size_t)b * NPTS * 64;
    float* Db = Dout + (size_t)b * NPTS * NPTS;

    int row = tid >> 1, half = tid & 1;
    {   // stage query tile transposed + norm partials
        const float4* r = (const float4*)(xb + (size_t)(q0 + row) * 64 + half * 32);
        float s = 0.f;
        #pragma unroll
        for (int c4 = 0; c4 < 8; c4++) {
            float4 v = r[c4];
            int c = half * 32 + c4 * 4;
            xq_t[(c+0)*128 + row] = v.x; xq_t[(c+1)*128 + row] = v.y;
            xq_t[(c+2)*128 + row] = v.z; xq_t[(c+3)*128 + row] = v.w;
            s += v.x*v.x + v.y*v.y + v.z*v.z + v.w*v.w;
        }
        psc[tid] = s;
    }
    {   // stage candidate tile transposed + norm partials
        const float4* r = (const float4*)(xb + (size_t)(c0 + row) * 64 + half * 32);
        float s = 0.f;
        #pragma unroll
        for (int c4 = 0; c4 < 8; c4++) {
            float4 v = r[c4];
            int c = half * 32 + c4 * 4;
            xc_t[(c+0)*128 + row] = v.x; xc_t[(c+1)*128 + row] = v.y;
            xc_t[(c+2)*128 + row] = v.z; xc_t[(c+3)*128 + row] = v.w;
            s += v.x*v.x + v.y*v.y + v.z*v.z + v.w*v.w;
        }
        psc[256 + tid] = s;
    }
    __syncthreads();
    if (tid < 128) {
        sqq[tid] = psc[2*tid] + psc[2*tid+1];
        sqc[tid] = psc[256 + 2*tid] + psc[256 + 2*tid+1];
    }
    __syncthreads();

    int tr = tid >> 4, tc = tid & 15;
    int m0 = tr * 8, n0 = tc * 8;
    float acc[8][8];
    #pragma unroll
    for (int r = 0; r < 8; r++)
        #pragma unroll
        for (int c = 0; c < 8; c++) acc[r][c] = 0.f;

    #pragma unroll 4
    for (int k = 0; k < 64; k++) {
        float4 a01 = *(const float4*)(xq_t + k * 128 + m0);
        float4 a23 = *(const float4*)(xq_t + k * 128 + m0 + 4);
        float4 w01 = *(const float4*)(xc_t + k * 128 + n0);
        float4 w23 = *(const float4*)(xc_t + k * 128 + n0 + 4);
        float av[8] = {a01.x,a01.y,a01.z,a01.w,a23.x,a23.y,a23.z,a23.w};
        float wv[8] = {w01.x,w01.y,w01.z,w01.w,w23.x,w23.y,w23.z,w23.w};
        #pragma unroll
        for (int r = 0; r < 8; r++)
            #pragma unroll
            for (int c = 0; c < 8; c++) acc[r][c] += av[r] * wv[c];
    }

    // epilogue: distances + store
    {
        float4 s01 = *(const float4*)(sqc + n0);
        float4 s23 = *(const float4*)(sqc + n0 + 4);
        float sv[8] = {s01.x,s01.y,s01.z,s01.w,s23.x,s23.y,s23.z,s23.w};
        #pragma unroll
        for (int r = 0; r < 8; r++) {
            float sq = sqq[m0 + r];
            float4 o0, o1;
            o0.x = (sq + sv[0]) - 2.f * acc[r][0];
            o0.y = (sq + sv[1]) - 2.f * acc[r][1];
            o0.z = (sq + sv[2]) - 2.f * acc[r][2];
            o0.w = (sq + sv[3]) - 2.f * acc[r][3];
            o1.x = (sq + sv[4]) - 2.f * acc[r][4];
            o1.y = (sq + sv[5]) - 2.f * acc[r][5];
            o1.z = (sq + sv[6]) - 2.f * acc[r][6];
            o1.w = (sq + sv[7]) - 2.f * acc[r][7];
            float* drow = Db + (size_t)(q0 + m0 + r) * NPTS + c0 + n0;
            *(float4*)(drow)     = o0;
            *(float4*)(drow + 4) = o1;
        }
    }
}

// ============================================================================
// Selection: 1 thread per query streams its 1024-float D row, register
// top-16 (strict < ascending j == lax.top_k tie policy).
// ============================================================================
__global__ __launch_bounds__(256) void sel_kernel(const float* __restrict__ D,
                                                  int* __restrict__ idx_out) {
    int gq  = blockIdx.x * 256 + threadIdx.x;
    int b   = gq >> 10;
    int q   = gq & (NPTS - 1);
    const float4* row = (const float4*)(D + (size_t)b * NPTS * NPTS + (size_t)q * NPTS);

    float td[KNNK];
    int   ti[KNNK];
    #pragma unroll
    for (int k = 0; k < KNNK; k++) { td[k] = INFINITY; ti[k] = 0; }
    float cmax = INFINITY;

    #pragma unroll 2
    for (int j4 = 0; j4 < NPTS / 4; ++j4) {
        float4 v = row[j4];
        int j = j4 * 4;
        #pragma unroll
        for (int u = 0; u < 4; u++) {
            float d = (u == 0) ? v.x : (u == 1) ? v.y : (u == 2) ? v.z : v.w;
            if (d < cmax) {
                td[KNNK - 1] = d;
                ti[KNNK - 1] = j + u;
                #pragma unroll
                for (int s = KNNK - 1; s > 0; --s) {
                    if (td[s] < td[s - 1]) {
                        float tv = td[s]; td[s] = td[s - 1]; td[s - 1] = tv;
                        int   iv = ti[s]; ti[s] = ti[s - 1]; ti[s - 1] = iv;
                    }
                }
                cmax = td[KNNK - 1];
            }
        }
    }
    #pragma unroll
    for (int k = 0; k < KNNK; k++)
        idx_out[(size_t)gq * KNNK + k] = ti[k];
}

// ============================================================================
// Precompute: A = x@(W1a-W1b)+b1, Bm = x@W1b.  One GEMM [128 pts x C]@[C x 128]
// per block; 256 thr as 16x16 grid, 8x8 register tiles.
// ============================================================================
template <int C>
__host__ __device__ constexpr size_t pre_smem() {
    return (size_t)(2 * C * 128 + 64) * 4;
}

template <int C>
__global__ __launch_bounds__(256) void pre_kernel(
    const float* __restrict__ x, const float* __restrict__ w1,
    const float* __restrict__ b1,
    float* __restrict__ A, float* __restrict__ Bm) {
    extern __shared__ __align__(16) float sm[];
    float* xt  = sm;             // C x 128 (k-major)
    float* wc  = xt + C * 128;   // C x 128: [ W1a-W1b | W1b ]
    float* b1s = wc + C * 128;   // 64

    int tid = threadIdx.x;
    int p0  = blockIdx.x * 128;

    for (int u = tid; u < C * 128; u += 256) {
        int c = u >> 7, j = u & 127;
        float v;
        if (j < 64) v = w1[c * 64 + j] - w1[(C + c) * 64 + j];
        else        v = w1[(C + c) * 64 + (j - 64)];
        wc[u] = v;
    }
    if constexpr (C == 1) {
        if (tid < 128) xt[tid] = x[p0 + tid];
    } else {
        int row = tid >> 1, half = tid & 1;
        const float4* r = (const float4*)(x + (size_t)(p0 + row) * C + half * 32);
        #pragma unroll
        for (int c4 = 0; c4 < 8; c4++) {
            float4 v = r[c4];
            int c = half * 32 + c4 * 4;
            xt[(c+0)*128 + row] = v.x; xt[(c+1)*128 + row] = v.y;
            xt[(c+2)*128 + row] = v.z; xt[(c+3)*128 + row] = v.w;
        }
    }
    if (tid < 64) b1s[tid] = b1[tid];
    __syncthreads();

    int tr = tid >> 4, tc = tid & 15;
    int m0 = tr * 8, n0 = tc * 8;
    float acc[8][8];
    #pragma unroll
    for (int r = 0; r < 8; r++)
        #pragma unroll
        for (int c = 0; c < 8; c++) acc[r][c] = 0.f;

    #pragma unroll 4
    for (int k = 0; k < C; k++) {
        float4 a01 = *(const float4*)(xt + k * 128 + m0);
        float4 a23 = *(const float4*)(xt + k * 128 + m0 + 4);
        float4 w01 = *(const float4*)(wc + k * 128 + n0);
        float4 w23 = *(const float4*)(wc + k * 128 + n0 + 4);
        float av[8] = {a01.x,a01.y,a01.z,a01.w,a23.x,a23.y,a23.z,a23.w};
        float wv[8] = {w01.x,w01.y,w01.z,w01.w,w23.x,w23.y,w23.z,w23.w};
        #pragma unroll
        for (int r = 0; r < 8; r++)
            #pragma unroll
            for (int c = 0; c < 8; c++) acc[r][c] += av[r] * wv[c];
    }

    if (tc < 8) {
        #pragma unroll
        for (int r = 0; r < 8; r++) {
            int p = p0 + m0 + r;
            float4 o0, o1;
            o0.x = acc[r][0] + b1s[n0+0]; o0.y = acc[r][1] + b1s[n0+1];
            o0.z = acc[r][2] + b1s[n0+2]; o0.w = acc[r][3] + b1s[n0+3];
            o1.x = acc[r][4] + b1s[n0+4]; o1.y = acc[r][5] + b1s[n0+5];
            o1.z = acc[r][6] + b1s[n0+6]; o1.w = acc[r][7] + b1s[n0+7];
            *(float4*)(A + (size_t)p * 64 + n0)     = o0;
            *(float4*)(A + (size_t)p * 64 + n0 + 4) = o1;
        }
    } else {
        int nb = n0 - 64;
        #pragma unroll
        for (int r = 0; r < 8; r++) {
            int p = p0 + m0 + r;
            float4 o0 = {acc[r][0], acc[r][1], acc[r][2], acc[r][3]};
            float4 o1 = {acc[r][4], acc[r][5], acc[r][6], acc[r][7]};
            *(float4*)(Bm + (size_t)p * 64 + nb)     = o0;
            *(float4*)(Bm + (size_t)p * 64 + nb + 4) = o1;
        }
    }
}

// ============================================================================
// Edge stage 2: h1[edge] = relu(A[i] + Bm[nbr]); out[i] = max_k (h1@W2 + b2).
// 256 thr = 4 groups x 64; group does 4 points -> M=64 edge rows, N=64,
// 8x8 thread grid with 8x8 register tiles (16:1 FMA:LDS).
// nidx holds BATCH-LOCAL indices; convert with the block's batch base.
// ============================================================================
__host__ __device__ constexpr int eg_grp() { return 4096 + 256 + 512 + 64; }
__host__ __device__ constexpr size_t edge2_smem() {
    return (size_t)(4096 + 64 + 4 * eg_grp()) * 4;
}

__global__ __launch_bounds__(256, 2) void edge2_kernel(
    const float* __restrict__ A, const float* __restrict__ Bm,
    const int* __restrict__ nidx,
    const float* __restrict__ w2, const float* __restrict__ b2,
    float* __restrict__ out) {
    extern __shared__ __align__(16) float sm[];
    float* w2s = sm;           // 64x64 k-major (row-major w2 already is)
    float* b2s = w2s + 4096;   // 64
    float* grp = b2s + 64;

    int tid = threadIdx.x, g = tid >> 6, t = tid & 63;
    float* h1t = grp + g * eg_grp();   // [c][m] 64x64
    float* ais = h1t + 4096;           // 4x64
    float* red = ais + 256;            // 8x64
    int*   nbrs = (int*)(red + 512);   // 64

    for (int u = tid; u < 4096; u += 256) w2s[u] = w2[u];
    if (tid < 64) b2s[tid] = b2[tid];
    __syncthreads();

    int gp = blockIdx.x * 16 + g * 4;
    int batch_base = (gp >> 10) << 10;   // batch start (global point id)
    int bid = g + 1;

    #pragma unroll
    for (int pt = 0; pt < 4; pt++) ais[pt * 64 + t] = A[(size_t)(gp + pt) * 64 + t];
    nbrs[t] = nidx[(size_t)gp * KNNK + t];
    gbar(bid, 64);

    {   // gather + relu -> h1t (k-major)
        int pt = t >> 4;
        int nb = batch_base + nbrs[t];   // batch-local -> global
        const float4* bv4 = (const float4*)(Bm + (size_t)nb * 64);
        const float4* av4 = (const float4*)(ais + pt * 64);
        #pragma unroll
        for (int c4 = 0; c4 < 16; c4++) {
            float4 bv = bv4[c4], av = av4[c4];
            int c = c4 * 4;
            h1t[(c+0)*64 + t] = fmaxf(av.x + bv.x, 0.f);
            h1t[(c+1)*64 + t] = fmaxf(av.y + bv.y, 0.f);
            h1t[(c+2)*64 + t] = fmaxf(av.z + bv.z, 0.f);
            h1t[(c+3)*64 + t] = fmaxf(av.w + bv.w, 0.f);
        }
    }
    gbar(bid, 64);

    int tr = t >> 3, tc = t & 7;
    int m0 = tr * 8, n0 = tc * 8;
    float acc[8][8];
    #pragma unroll
    for (int r = 0; r < 8; r++)
        #pragma unroll
        for (int c = 0; c < 8; c++) acc[r][c] = 0.f;

    #pragma unroll 4
    for (int k = 0; k < HID; k++) {
        float4 a01 = *(const float4*)(h1t + k * 64 + m0);
        float4 a23 = *(const float4*)(h1t + k * 64 + m0 + 4);
        float4 w01 = *(const float4*)(w2s + k * 64 + n0);
        float4 w23 = *(const float4*)(w2s + k * 64 + n0 + 4);
        float av[8] = {a01.x,a01.y,a01.z,a01.w,a23.x,a23.y,a23.z,a23.w};
        float wv[8] = {w01.x,w01.y,w01.z,w01.w,w23.x,w23.y,w23.z,w23.w};
        #pragma unroll
        for (int r = 0; r < 8; r++)
            #pragma unroll
            for (int c = 0; c < 8; c++) acc[r][c] += av[r] * wv[c];
    }

    // partial max over this thread's 8 rows (8 neighbors of one point-half)
    float pm[8];
    #pragma unroll
    for (int c = 0; c < 8; c++) {
        float m = acc[0][c];
        #pragma unroll
        for (int r = 1; r < 8; r++) m = fmaxf(m, acc[r][c]);
        pm[c] = m;
    }
    *(float4*)(red + tr * 64 + n0)     = make_float4(pm[0], pm[1], pm[2], pm[3]);
    *(float4*)(red + tr * 64 + n0 + 4) = make_float4(pm[4], pm[5], pm[6], pm[7]);
    gbar(bid, 64);

    #pragma unroll
    for (int pt = 0; pt < 4; pt++) {
        float v = fmaxf(red[(2*pt) * 64 + t], red[(2*pt+1) * 64 + t]) + b2s[t];
        out[(size_t)(gp + pt) * 64 + t] = v;
    }
}

// ============================================================================
// Final MLP: 4-way split accumulators for ILP
// ============================================================================
#define MLP_GSZ (192 + 128 + 64 + 32 + 4)
__host__ __device__ constexpr size_t mlp_smem_bytes() {
    return (size_t)(192*128 + 128*64 + 64*32 + 32*2 + 128 + 64 + 32 + 4
                    + 2 * MLP_GSZ) * 4;
}

__global__ __launch_bounds__(256) void mlp_kernel(
    const float* __restrict__ x1, const float* __restrict__ x2,
    const float* __restrict__ x3,
    const float* __restrict__ mw1, const float* __restrict__ mb1,
    const float* __restrict__ mw2, const float* __restrict__ mb2,
    const float* __restrict__ mw3, const float* __restrict__ mb3,
    const float* __restrict__ mw4, const float* __restrict__ mb4,
    float* __restrict__ out) {
    extern __shared__ __align__(16) float sm[];
    float* w1s = sm;
    float* w2s = w1s + 192 * 128;
    float* w3s = w2s + 128 * 64;
    float* w4s = w3s + 64 * 32;
    float* b1s = w4s + 64;
    float* b2s = b1s + 128;
    float* b3s = b2s + 64;
    float* b4s = b3s + 32;
    float* grp = b4s + 4;

    int tid = threadIdx.x;
    int g   = tid >> 7;
    int t   = tid & 127;
    float* feat = grp + g * MLP_GSZ;
    float* h1   = feat + 192;
    float* h2   = h1 + 128;
    float* h3   = h2 + 64;
    float* oo   = h3 + 32;

    for (int u = tid; u < 192 * 128; u += 256) w1s[u] = mw1[u];
    for (int u = tid; u < 128 * 64;  u += 256) w2s[u] = mw2[u];
    for (int u = tid; u < 64 * 32;   u += 256) w3s[u] = mw3[u];
    if (tid < 64)  w4s[tid] = mw4[tid];
    if (tid < 128) b1s[tid] = mb1[tid];
    if (tid < 64)  b2s[tid] = mb2[tid];
    if (tid < 32)  b3s[tid] = mb3[tid];
    if (tid < 2)   b4s[tid] = mb4[tid];
    __syncthreads();

    constexpr int PTSG = 16;
    int base = blockIdx.x * (2 * PTSG) + g * PTSG;
    int bid  = g + 1;

    for (int p = 0; p < PTSG; ++p) {
        int gi = base + p;
        if (t < 64) {
            feat[t]       = x1[(size_t)gi * 64 + t];
            feat[64 + t]  = x2[(size_t)gi * 64 + t];
            feat[128 + t] = x3[(size_t)gi * 64 + t];
        }
        gbar(bid, 128);

        {
            float a0=0,a1=0,a2=0,a3=0;
            const float4* f4 = reinterpret_cast<const float4*>(feat);
            #pragma unroll 8
            for (int c4 = 0; c4 < 48; c4++) {
                float4 f = f4[c4];
                int c = c4 * 4;
                a0 += f.x * w1s[(c+0)*128 + t];
                a1 += f.y * w1s[(c+1)*128 + t];
                a2 += f.z * w1s[(c+2)*128 + t];
                a3 += f.w * w1s[(c+3)*128 + t];
            }
            h1[t] = fmaxf(((a0+a1)+(a2+a3)) + b1s[t], 0.f);
        }
        gbar(bid, 128);

        if (t < 64) {
            float a0=0,a1=0,a2=0,a3=0;
            const float4* f4 = reinterpret_cast<const float4*>(h1);
            #pragma unroll 8
            for (int c4 = 0; c4 < 32; c4++) {
                float4 f = f4[c4];
                int c = c4 * 4;
                a0 += f.x * w2s[(c+0)*64 + t];
                a1 += f.y * w2s[(c+1)*64 + t];
                a2 += f.z * w2s[(c+2)*64 + t];
                a3 += f.w * w2s[(c+3)*64 + t];
            }
            h2[t] = fmaxf(((a0+a1)+(a2+a3)) + b2s[t], 0.f);
        }
        gbar(bid, 128);

        if (t < 32) {
            float a0=0,a1=0,a2=0,a3=0;
            const float4* f4 = reinterpret_cast<const float4*>(h2);
            #pragma unroll
            for (int c4 = 0; c4 < 16; c4++) {
                float4 f = f4[c4];
                int c = c4 * 4;
                a0 += f.x * w3s[(c+0)*32 + t];
                a1 += f.y * w3s[(c+1)*32 + t];
                a2 += f.z * w3s[(c+2)*32 + t];
                a3 += f.w * w3s[(c+3)*32 + t];
            }
            h3[t] = fmaxf(((a0+a1)+(a2+a3)) + b3s[t], 0.f);
        }
        gbar(bid, 128);

        if (t < 2) {
            float acc = 0.f;
            #pragma unroll
            for (int c = 0; c < 32; c++) acc += h3[c] * w4s[c * 2 + t];
            oo[t] = acc + b4s[t];
        }
        gbar(bid, 128);

        if (t == 0) {
            float o0 = oo[0], o1 = oo[1];
            float m = fmaxf(o0, o1);
            float l = m + logf(expf(o0 - m) + expf(o1 - m));
            out[(size_t)gi * 2 + 0] = o0 - l;
            out[(size_t)gi * 2 + 1] = o1 - l;
        }
        gbar(bid, 128);
    }
}

// ============================================================================
// Launch
// ============================================================================
extern "C" void kernel_launch(void* const* d_in, const int* in_sizes, int n_in,
                              void* d_out, int out_size) {
    const float* x    = (const float*)d_in[0];
    const float* c1w1 = (const float*)d_in[1];
    const float* c1b1 = (const float*)d_in[2];
    const float* c1w2 = (const float*)d_in[3];
    const float* c1b2 = (const float*)d_in[4];
    const float* c2w1 = (const float*)d_in[5];
    const float* c2b1 = (const float*)d_in[6];
    const float* c2w2 = (const float*)d_in[7];
    const float* c2b2 = (const float*)d_in[8];
    const float* c3w1 = (const float*)d_in[9];
    const float* c3b1 = (const float*)d_in[10];
    const float* c3w2 = (const float*)d_in[11];
    const float* c3b2 = (const float*)d_in[12];
    const float* mw1  = (const float*)d_in[13];
    const float* mb1  = (const float*)d_in[14];
    const float* mw2  = (const float*)d_in[15];
    const float* mb2  = (const float*)d_in[16];
    const float* mw3  = (const float*)d_in[17];
    const float* mb3  = (const float*)d_in[18];
    const float* mw4  = (const float*)d_in[19];
    const float* mb4  = (const float*)d_in[20];
    float* out = (float*)d_out;

    float *x1p, *x2p, *x3p, *Ap, *Bp, *Dp;
    int* idxp;
    cudaGetSymbolAddress((void**)&x1p, g_x1);
    cudaGetSymbolAddress((void**)&x2p, g_x2);
    cudaGetSymbolAddress((void**)&x3p, g_x3);
    cudaGetSymbolAddress((void**)&Ap,  g_A);
    cudaGetSymbolAddress((void**)&Bp,  g_Bm);
    cudaGetSymbolAddress((void**)&Dp,  g_D);
    cudaGetSymbolAddress((void**)&idxp, g_idx);

    size_t d_smem   = dist_smem();
    size_t p64_smem = pre_smem<64>();
    size_t p1_smem  = pre_smem<1>();
    size_t e2_smem  = edge2_smem();
    size_t ml_smem  = mlp_smem_bytes();
    cudaFuncSetAttribute(dist_kernel,
                         cudaFuncAttributeMaxDynamicSharedMemorySize, (int)d_smem);
    cudaFuncSetAttribute(pre_kernel<64>,
                         cudaFuncAttributeMaxDynamicSharedMemorySize, (int)p64_smem);
    cudaFuncSetAttribute(edge2_kernel,
                         cudaFuncAttributeMaxDynamicSharedMemorySize, (int)e2_smem);
    cudaFuncSetAttribute(mlp_kernel,
                         cudaFuncAttributeMaxDynamicSharedMemorySize, (int)ml_smem);

    dim3 knn1_grid(BATCH * (NPTS / 128));   // 512
    dim3 dist_grid(BATCH * 64);             // 4096 (8x8 tiles per batch)
    dim3 sel_grid(TOTALPTS / 256);          // 256
    dim3 pre_grid(TOTALPTS / 128);          // 512
    dim3 e2_grid(TOTALPTS / 16);            // 4096
    dim3 mlp_grid(TOTALPTS / 32);           // 2048

    // conv1
    knn1_kernel<<<knn1_grid, 128>>>(x, idxp);
    pre_kernel<1><<<pre_grid, 256, p1_smem>>>(x, c1w1, c1b1, Ap, Bp);
    edge2_kernel<<<e2_grid, 256, e2_smem>>>(Ap, Bp, idxp, c1w2, c1b2, x1p);
    // conv2
    dist_kernel<<<dist_grid, 256, d_smem>>>(x1p, Dp);
    sel_kernel<<<sel_grid, 256>>>(Dp, idxp);
    pre_kernel<64><<<pre_grid, 256, p64_smem>>>(x1p, c2w1, c2b1, Ap, Bp);
    edge2_kernel<<<e2_grid, 256, e2_smem>>>(Ap, Bp, idxp, c2w2, c2b2, x2p);
    // conv3
    dist_kernel<<<dist_grid, 256, d_smem>>>(x2p, Dp);
    sel_kernel<<<sel_grid, 256>>>(Dp, idxp);
    pre_kernel<64><<<pre_grid, 256, p64_smem>>>(x2p, c3w1, c3b1, Ap, Bp);
    edge2_kernel<<<e2_grid, 256, e2_smem>>>(Ap, Bp, idxp, c3w2, c3b2, x3p);
    // head
    mlp_kernel<<<mlp_grid, 256, ml_smem>>>(x1p, x2p, x3p,
                                           mw1, mb1, mw2, mb2, mw3, mb3, mw4, mb4, out);
}